// round 3
// baseline (speedup 1.0000x reference)
#include <cuda_runtime.h>
#include <math.h>

#define LL 2048
#define NROWS 8192   // B*L

// ---------------- scratch (device globals; no runtime allocation) ----------------
static __device__ float g_zx [NROWS * 3088]; // zxbcdt
static __device__ float g_X  [NROWS * 1024]; // silu(conv) x part
static __device__ float g_Bm [NROWS * 512];
static __device__ float g_Cm [NROWS * 512];
static __device__ float g_dt [NROWS * 16];
static __device__ float g_dec[NROWS * 16];
static __device__ float g_yp [256 * LL * 64]; // y partials per (b,head,nblock)
static __device__ float g_g  [NROWS * 1024]; // gated
static __device__ float g_res[NROWS * 512];  // pre-norm residual

// ---------------- generic fp32 SIMT GEMM: C = A(MxK) @ B(KxN) [+ Res] ------------
template<int Nv, int Kv, bool GUARD, bool ADDRES>
__device__ __forceinline__ void gemm_body(const float* __restrict__ A,
                                          const float* __restrict__ Bw,
                                          float* __restrict__ C,
                                          const float* __restrict__ Res)
{
    __shared__ __align__(16) float As[8][128];
    __shared__ __align__(16) float Bs[8][128];
    const int tid  = threadIdx.x;
    const int tx   = tid & 15;
    const int ty   = tid >> 4;
    const int aRow = tid >> 1;
    const int aCol = (tid & 1) * 4;
    const int bRow = tid >> 5;
    const int bCol = (tid & 31) * 4;
    const int nbase = blockIdx.x * 128;
    const int mbase = blockIdx.y * 128;
    const float* Ap = A + (size_t)mbase * Kv;

    float acc[8][8];
#pragma unroll
    for (int i = 0; i < 8; i++)
#pragma unroll
        for (int j = 0; j < 8; j++) acc[i][j] = 0.f;

    for (int k0 = 0; k0 < Kv; k0 += 8) {
        float4 av = *(const float4*)(Ap + (size_t)aRow * Kv + k0 + aCol);
        As[aCol + 0][aRow] = av.x;
        As[aCol + 1][aRow] = av.y;
        As[aCol + 2][aRow] = av.z;
        As[aCol + 3][aRow] = av.w;
        float4 bv = make_float4(0.f, 0.f, 0.f, 0.f);
        if (!GUARD || (nbase + bCol + 3 < Nv))
            bv = *(const float4*)(Bw + (size_t)(k0 + bRow) * Nv + nbase + bCol);
        *(float4*)&Bs[bRow][bCol] = bv;
        __syncthreads();
#pragma unroll
        for (int kk = 0; kk < 8; kk++) {
            float4 a0 = *(const float4*)&As[kk][ty * 8];
            float4 a1 = *(const float4*)&As[kk][ty * 8 + 4];
            float4 b0 = *(const float4*)&Bs[kk][tx * 8];
            float4 b1 = *(const float4*)&Bs[kk][tx * 8 + 4];
            float ra[8] = {a0.x, a0.y, a0.z, a0.w, a1.x, a1.y, a1.z, a1.w};
            float rb[8] = {b0.x, b0.y, b0.z, b0.w, b1.x, b1.y, b1.z, b1.w};
#pragma unroll
            for (int i = 0; i < 8; i++)
#pragma unroll
                for (int j = 0; j < 8; j++)
                    acc[i][j] = fmaf(ra[i], rb[j], acc[i][j]);
        }
        __syncthreads();
    }
#pragma unroll
    for (int i = 0; i < 8; i++) {
        const int row = mbase + ty * 8 + i;
#pragma unroll
        for (int j = 0; j < 8; j++) {
            const int col = nbase + tx * 8 + j;
            if (!GUARD || col < Nv) {
                float v = acc[i][j];
                if (ADDRES) v += Res[(size_t)row * Nv + col];
                C[(size_t)row * Nv + col] = v;
            }
        }
    }
}

__global__ void __launch_bounds__(256) gemm1_kernel(const float* __restrict__ A,
                                                    const float* __restrict__ W)
{
    gemm_body<3088, 512, true, false>(A, W, g_zx, nullptr);
}

__global__ void __launch_bounds__(256) gemm2_kernel(const float* __restrict__ W,
                                                    const float* __restrict__ Res)
{
    gemm_body<512, 1024, false, true>(g_g, W, g_res, Res);
}

// ---------------- conv1d (K=4, causal) + bias + silu + split ----------------------
__global__ void conv_kernel(const float* __restrict__ conv_w,
                            const float* __restrict__ conv_b)
{
    const int idx = blockIdx.x * blockDim.x + threadIdx.x; // [0, 8192*2048)
    const int c   = idx & 2047;
    const int row = idx >> 11;
    const int t   = row & (LL - 1);
    float acc = conv_b[c];
#pragma unroll
    for (int k = 0; k < 4; k++) {
        const int tt = t - 3 + k;
        if (tt >= 0)
            acc = fmaf(g_zx[(size_t)(row - (3 - k)) * 3088 + 1024 + c], conv_w[c * 4 + k], acc);
    }
    const float v = acc / (1.f + expf(-acc)); // silu
    if (c < 1024)       g_X [(size_t)row * 1024 + c]          = v;
    else if (c < 1536)  g_Bm[(size_t)row * 512  + (c - 1024)] = v;
    else                g_Cm[(size_t)row * 512  + (c - 1536)] = v;
}

// ---------------- dt / decay ------------------------------------------------------
__global__ void dt_kernel(const float* __restrict__ dt_bias,
                          const float* __restrict__ A_log)
{
    const int idx = blockIdx.x * blockDim.x + threadIdx.x; // [0, 8192*16)
    const int h   = idx & 15;
    const int row = idx >> 4;
    const float x  = g_zx[(size_t)row * 3088 + 3072 + h] + dt_bias[h];
    const float dt = (x > 20.f) ? x : log1pf(expf(x));
    g_dt [idx] = dt;
    g_dec[idx] = expf(-expf(A_log[h]) * dt);
}

// ---------------- selective scan --------------------------------------------------
// Grid: 256 CTAs = (b, head, nblock of 32 states). 128 threads.
// Thread tid: n_l = tid&31 (state index within block), pq = tid>>5 (owns p = pq*4..pq*4+3).
// Per step: h[n][p] = dec*h + dt * sum_r B[n][r]*X[r][p]; y[r,p] = sum_n C[n][r]*h[n][p].
// y computed from an smem copy of h (stride-33 layout, conflict-free) by threads mapped
// to (r,p) pairs; partial (32-state) sums written to g_yp, combined later.
__global__ void __launch_bounds__(128) scan_kernel()
{
    const int bx = blockIdx.x;
    const int nb = bx & 3;
    const int bh = bx >> 2;
    const int hh = bh & 15;
    const int bb = bh >> 4;
    const int tid  = threadIdx.x;
    const int n_l  = tid & 31;
    const int pq   = tid >> 5;
    const int pair = tid >> 1;
    const int half = tid & 1;
    const int rY   = pair >> 4;
    const int pY   = pair & 15;

    __shared__ __align__(16) float sB[4][32][4];
    __shared__ __align__(16) float sC[4][4][33];
    __shared__ __align__(16) float sX[4][64];
    __shared__ __align__(16) float sS[4][2];
    __shared__ __align__(16) float sH[2][16][33];

    const float* Bsrc = g_Bm  + (size_t)bb * LL * 512  + nb * 128;
    const float* Csrc = g_Cm  + (size_t)bb * LL * 512  + nb * 128;
    const float* Xsrc = g_X   + (size_t)bb * LL * 1024 + hh * 64;
    const float* Dsrc = g_dec + (size_t)bb * LL * 16   + hh;
    const float* Tsrc = g_dt  + (size_t)bb * LL * 16   + hh;
    float* Ydst = g_yp + (size_t)bx * LL * 64;

    // prologue: stage t = 0,1,2
    for (int s = 0; s < 3; s++) {
        if (tid < 32) {
            float4 v = *(const float4*)(Bsrc + (size_t)s * 512 + tid * 4);
            *(float4*)&sB[s][tid][0] = v;
        } else if (tid < 64) {
            const int n = tid - 32;
            float4 v = *(const float4*)(Csrc + (size_t)s * 512 + n * 4);
            sC[s][0][n] = v.x; sC[s][1][n] = v.y; sC[s][2][n] = v.z; sC[s][3][n] = v.w;
        } else if (tid < 80) {
            const int i = tid - 64;
            float4 v = *(const float4*)(Xsrc + (size_t)s * 1024 + i * 4);
            *(float4*)&sX[s][i * 4] = v;
        } else if (tid == 80) sS[s][0] = Dsrc[(size_t)s * 16];
        else if (tid == 81)   sS[s][1] = Tsrc[(size_t)s * 16];
    }
    __syncthreads();

    float h0 = 0.f, h1 = 0.f, h2 = 0.f, h3 = 0.f;

    for (int t = 0; t < LL; t++) {
        const int cb = t & 3;
        const int hb = t & 1;
        // ---- state update ----
        const float4 Bv = *(const float4*)&sB[cb][n_l][0];
        const float dec = sS[cb][0];
        const float dtv = sS[cb][1];
        const float4 X0 = *(const float4*)&sX[cb][ 0 + pq * 4];
        const float4 X1 = *(const float4*)&sX[cb][16 + pq * 4];
        const float4 X2 = *(const float4*)&sX[cb][32 + pq * 4];
        const float4 X3 = *(const float4*)&sX[cb][48 + pq * 4];
        const float u0 = Bv.x * X0.x + Bv.y * X1.x + Bv.z * X2.x + Bv.w * X3.x;
        const float u1 = Bv.x * X0.y + Bv.y * X1.y + Bv.z * X2.y + Bv.w * X3.y;
        const float u2 = Bv.x * X0.z + Bv.y * X1.z + Bv.z * X2.z + Bv.w * X3.z;
        const float u3 = Bv.x * X0.w + Bv.y * X1.w + Bv.z * X2.w + Bv.w * X3.w;
        h0 = fmaf(dec, h0, dtv * u0);
        h1 = fmaf(dec, h1, dtv * u1);
        h2 = fmaf(dec, h2, dtv * u2);
        h3 = fmaf(dec, h3, dtv * u3);

        // ---- prefetch (depth 3) ----
        const int tp = t + 3;
        float4 rv = make_float4(0.f, 0.f, 0.f, 0.f);
        float  rsv = 0.f;
        const bool doPre = (tp < LL);
        if (doPre) {
            if (tid < 32)       rv = *(const float4*)(Bsrc + (size_t)tp * 512 + tid * 4);
            else if (tid < 64)  rv = *(const float4*)(Csrc + (size_t)tp * 512 + (tid - 32) * 4);
            else if (tid < 80)  rv = *(const float4*)(Xsrc + (size_t)tp * 1024 + (tid - 64) * 4);
            else if (tid == 80) rsv = Dsrc[(size_t)tp * 16];
            else if (tid == 81) rsv = Tsrc[(size_t)tp * 16];
        }

        // ---- publish h ----
        const int pbase = pq * 4;
        sH[hb][pbase + 0][n_l] = h0;
        sH[hb][pbase + 1][n_l] = h1;
        sH[hb][pbase + 2][n_l] = h2;
        sH[hb][pbase + 3][n_l] = h3;
        __syncthreads();

        if (doPre) {
            const int buf = tp & 3;
            if (tid < 32) *(float4*)&sB[buf][tid][0] = rv;
            else if (tid < 64) {
                const int n = tid - 32;
                sC[buf][0][n] = rv.x; sC[buf][1][n] = rv.y; sC[buf][2][n] = rv.z; sC[buf][3][n] = rv.w;
            } else if (tid < 80) *(float4*)&sX[buf][(tid - 64) * 4] = rv;
            else if (tid == 80) sS[buf][0] = rsv;
            else if (tid == 81) sS[buf][1] = rsv;
        }

        // ---- y = C^T h (partial over this n-block) ----
        const float* Crow = &sC[cb][rY][half * 16];
        const float* Hrow = &sH[hb][pY][half * 16];
        float acc = 0.f;
#pragma unroll
        for (int i = 0; i < 16; i++) acc = fmaf(Crow[i], Hrow[i], acc);
        acc += __shfl_xor_sync(0xffffffffu, acc, 1);
        if (half == 0) Ydst[(size_t)t * 64 + pair] = acc;
        __syncthreads();
    }
}

// ---------------- combine partials + D_skip + z-gate ------------------------------
__global__ void combine_kernel(const float* __restrict__ D_skip)
{
    const int idx = blockIdx.x * blockDim.x + threadIdx.x; // [0, 8192*1024)
    const int c    = idx & 1023;
    const int row  = idx >> 10;
    const int head = c >> 6;
    const int d    = c & 63;
    const int b    = row >> 11;
    const int t    = row & (LL - 1);
    const int base = (b * 16 + head) * 4;
    float y = 0.f;
#pragma unroll
    for (int nb = 0; nb < 4; nb++)
        y += g_yp[(size_t)(base + nb) * LL * 64 + (size_t)t * 64 + d];
    const float x = g_X[(size_t)row * 1024 + c];
    y += x * D_skip[head];
    const float z = g_zx[(size_t)row * 3088 + c];
    g_g[(size_t)row * 1024 + c] = y * (z / (1.f + expf(-z)));
}

// ---------------- RMSNorm ---------------------------------------------------------
__global__ void __launch_bounds__(256) rms_kernel(float* __restrict__ out)
{
    const int warp = threadIdx.x >> 5;
    const int lane = threadIdx.x & 31;
    const int row  = blockIdx.x * 8 + warp;
    const float* r = g_res + (size_t)row * 512;
    float v[16];
    float ss = 0.f;
#pragma unroll
    for (int i = 0; i < 16; i++) { v[i] = r[lane + i * 32]; ss = fmaf(v[i], v[i], ss); }
#pragma unroll
    for (int o = 16; o >= 1; o >>= 1) ss += __shfl_xor_sync(0xffffffffu, ss, o);
    const float sc = rsqrtf(ss * (1.f / 512.f) + 1e-5f);
    float* o = out + (size_t)row * 512;
#pragma unroll
    for (int i = 0; i < 16; i++) o[lane + i * 32] = v[i] * sc;
}

// ---------------- launch ----------------------------------------------------------
extern "C" void kernel_launch(void* const* d_in, const int* in_sizes, int n_in,
                              void* d_out, int out_size)
{
    const float* hs      = (const float*)d_in[0];
    const float* W_in    = (const float*)d_in[1];
    const float* conv_w  = (const float*)d_in[2];
    const float* conv_b  = (const float*)d_in[3];
    const float* dt_bias = (const float*)d_in[4];
    const float* A_log   = (const float*)d_in[5];
    const float* D_skip  = (const float*)d_in[6];
    const float* W_out   = (const float*)d_in[7];
    float* out = (float*)d_out;

    gemm1_kernel<<<dim3(25, 64), 256>>>(hs, W_in);
    conv_kernel<<<NROWS * 2048 / 256, 256>>>(conv_w, conv_b);
    dt_kernel<<<NROWS * 16 / 256, 256>>>(dt_bias, A_log);
    scan_kernel<<<256, 128>>>();
    combine_kernel<<<NROWS * 1024 / 256, 256>>>(D_skip);
    gemm2_kernel<<<dim3(4, 64), 256>>>(W_out, hs);
    rms_kernel<<<NROWS / 8, 256>>>(out);
}

// round 5
// speedup vs baseline: 1.1550x; 1.1550x over previous
#include <cuda_runtime.h>
#include <math.h>
#include <stdint.h>

#define LL 2048
#define NROWS 8192   // B*L

// ---------------- scratch (device globals; no runtime allocation) ----------------
static __device__ float g_zx [NROWS * 3088]; // zxbcdt
static __device__ float g_X  [NROWS * 1024]; // silu(conv) x part
static __device__ float g_Bm [NROWS * 512];
static __device__ float g_Cm [NROWS * 512];
static __device__ float g_dt [NROWS * 16];
static __device__ float g_dec[NROWS * 16];
static __device__ float g_yp [256 * LL * 64]; // y partials per (b,head,nblock)
static __device__ float g_g  [NROWS * 1024]; // gated
static __device__ float g_res[NROWS * 512];  // pre-norm residual

// ---------------- tf32 helpers ----------------------------------------------------
__device__ __forceinline__ uint32_t f2tf32(float v) {
    uint32_t r;
    asm("cvt.rna.tf32.f32 %0, %1;" : "=r"(r) : "f"(v));
    return r;
}
__device__ __forceinline__ void split_tf32(float v, float& hi, float& lo) {
    uint32_t h = f2tf32(v);
    hi = __uint_as_float(h);
    float l = v - hi;                 // exact in fp32
    lo = __uint_as_float(f2tf32(l));
}
__device__ __forceinline__ void mma_tf32(float d[4],
                                         uint32_t a0, uint32_t a1, uint32_t a2, uint32_t a3,
                                         uint32_t b0, uint32_t b1) {
    asm volatile(
        "mma.sync.aligned.m16n8k8.row.col.f32.tf32.tf32.f32 "
        "{%0,%1,%2,%3}, {%4,%5,%6,%7}, {%8,%9}, {%0,%1,%2,%3};"
        : "+f"(d[0]), "+f"(d[1]), "+f"(d[2]), "+f"(d[3])
        : "r"(a0), "r"(a1), "r"(a2), "r"(a3), "r"(b0), "r"(b1));
}

// ---------------- TF32 tensor-core GEMM: C = A(MxK) @ B(KxN) [+ Res] --------------
// CTA tile 128x128, 8 warps as 2(M)x4(N) -> warp tile 64x32. k-slice = 8.
// 3-term tf32 split (hi*hi + hi*lo + lo*hi) for ~fp32 accuracy.
// smem stride 136 floats: fragment LDS bank = (8*tig + gid) -> conflict-free.
template<int Nv, int Kv, bool GUARD, bool ADDRES>
__device__ __forceinline__ void gemm_tf32_body(const float* __restrict__ A,
                                               const float* __restrict__ Bw,
                                               float* __restrict__ C,
                                               const float* __restrict__ Res)
{
    __shared__ __align__(16) float sA[2][2][8][136]; // [buf][hi/lo][k][row]
    __shared__ __align__(16) float sB[2][2][8][136]; // [buf][hi/lo][k][col]

    const int tid   = threadIdx.x;
    const int warp  = tid >> 5;
    const int lane  = tid & 31;
    const int gid   = lane >> 2;   // 0..7
    const int tig   = lane & 3;    // 0..3
    const int warpM = warp & 1;    // 0..1 (64 rows each)
    const int warpN = warp >> 1;   // 0..3 (32 cols each)

    const int aRow = tid >> 1;         // 0..127
    const int aCol = (tid & 1) * 4;    // 0 or 4
    const int bRow = tid >> 5;         // 0..7
    const int bCol = (tid & 31) * 4;   // 0..124

    const int nbase = blockIdx.x * 128;
    const int mbase = blockIdx.y * 128;
    const float* Ap = A + (size_t)(mbase + aRow) * Kv + aCol;
    const float* Bp = Bw + (size_t)bRow * Nv + nbase + bCol;
    const bool  bOK = (!GUARD) || (nbase + bCol + 3 < Nv);

    float acc[4][4][4];
#pragma unroll
    for (int mt = 0; mt < 4; mt++)
#pragma unroll
        for (int nt = 0; nt < 4; nt++)
#pragma unroll
            for (int i = 0; i < 4; i++) acc[mt][nt][i] = 0.f;

    // ---- fill buffer 0 ----
    {
        float4 av = *(const float4*)Ap;
        float4 bv = bOK ? *(const float4*)Bp : make_float4(0.f,0.f,0.f,0.f);
        float h, l;
        split_tf32(av.x, h, l); sA[0][0][aCol+0][aRow] = h; sA[0][1][aCol+0][aRow] = l;
        split_tf32(av.y, h, l); sA[0][0][aCol+1][aRow] = h; sA[0][1][aCol+1][aRow] = l;
        split_tf32(av.z, h, l); sA[0][0][aCol+2][aRow] = h; sA[0][1][aCol+2][aRow] = l;
        split_tf32(av.w, h, l); sA[0][0][aCol+3][aRow] = h; sA[0][1][aCol+3][aRow] = l;
        float4 bh, bl;
        split_tf32(bv.x, bh.x, bl.x); split_tf32(bv.y, bh.y, bl.y);
        split_tf32(bv.z, bh.z, bl.z); split_tf32(bv.w, bh.w, bl.w);
        *(float4*)&sB[0][0][bRow][bCol] = bh;
        *(float4*)&sB[0][1][bRow][bCol] = bl;
    }
    __syncthreads();

    const int NK = Kv / 8;
    for (int ks = 0; ks < NK; ks++) {
        const int buf = ks & 1;
        // ---- prefetch next slice (gmem -> regs) ----
        float4 av, bv;
        const bool hasNext = (ks + 1 < NK);
        if (hasNext) {
            av = *(const float4*)(Ap + (ks + 1) * 8);
            bv = bOK ? *(const float4*)(Bp + (size_t)(ks + 1) * 8 * Nv)
                     : make_float4(0.f,0.f,0.f,0.f);
        }

        // ---- fragment loads (conflict-free) ----
        const float (*Ah)[136] = sA[buf][0];
        const float (*Al)[136] = sA[buf][1];
        const float (*Bh)[136] = sB[buf][0];
        const float (*Bl)[136] = sB[buf][1];

        uint32_t ah[4][4], al[4][4], bh[4][2], bl[4][2];
#pragma unroll
        for (int mt = 0; mt < 4; mt++) {
            const int r = warpM * 64 + mt * 16 + gid;
            ah[mt][0] = __float_as_uint(Ah[tig    ][r    ]);
            ah[mt][1] = __float_as_uint(Ah[tig    ][r + 8]);
            ah[mt][2] = __float_as_uint(Ah[tig + 4][r    ]);
            ah[mt][3] = __float_as_uint(Ah[tig + 4][r + 8]);
            al[mt][0] = __float_as_uint(Al[tig    ][r    ]);
            al[mt][1] = __float_as_uint(Al[tig    ][r + 8]);
            al[mt][2] = __float_as_uint(Al[tig + 4][r    ]);
            al[mt][3] = __float_as_uint(Al[tig + 4][r + 8]);
        }
#pragma unroll
        for (int nt = 0; nt < 4; nt++) {
            const int c = warpN * 32 + nt * 8 + gid;
            bh[nt][0] = __float_as_uint(Bh[tig    ][c]);
            bh[nt][1] = __float_as_uint(Bh[tig + 4][c]);
            bl[nt][0] = __float_as_uint(Bl[tig    ][c]);
            bl[nt][1] = __float_as_uint(Bl[tig + 4][c]);
        }

        // ---- 3-term mma ----
#pragma unroll
        for (int mt = 0; mt < 4; mt++)
#pragma unroll
            for (int nt = 0; nt < 4; nt++) {
                mma_tf32(acc[mt][nt], ah[mt][0], ah[mt][1], ah[mt][2], ah[mt][3],
                         bh[nt][0], bh[nt][1]);
                mma_tf32(acc[mt][nt], ah[mt][0], ah[mt][1], ah[mt][2], ah[mt][3],
                         bl[nt][0], bl[nt][1]);
                mma_tf32(acc[mt][nt], al[mt][0], al[mt][1], al[mt][2], al[mt][3],
                         bh[nt][0], bh[nt][1]);
            }

        // ---- split + store next slice into other buffer ----
        if (hasNext) {
            const int nb = buf ^ 1;
            float h, l;
            split_tf32(av.x, h, l); sA[nb][0][aCol+0][aRow] = h; sA[nb][1][aCol+0][aRow] = l;
            split_tf32(av.y, h, l); sA[nb][0][aCol+1][aRow] = h; sA[nb][1][aCol+1][aRow] = l;
            split_tf32(av.z, h, l); sA[nb][0][aCol+2][aRow] = h; sA[nb][1][aCol+2][aRow] = l;
            split_tf32(av.w, h, l); sA[nb][0][aCol+3][aRow] = h; sA[nb][1][aCol+3][aRow] = l;
            float4 bhh, bll;
            split_tf32(bv.x, bhh.x, bll.x); split_tf32(bv.y, bhh.y, bll.y);
            split_tf32(bv.z, bhh.z, bll.z); split_tf32(bv.w, bhh.w, bll.w);
            *(float4*)&sB[nb][0][bRow][bCol] = bhh;
            *(float4*)&sB[nb][1][bRow][bCol] = bll;
        }
        __syncthreads();
    }

    // ---- epilogue ----
#pragma unroll
    for (int mt = 0; mt < 4; mt++) {
        const int row0 = mbase + warpM * 64 + mt * 16 + gid;
#pragma unroll
        for (int nt = 0; nt < 4; nt++) {
            const int col = nbase + warpN * 32 + nt * 8 + tig * 2;
            if (!GUARD || col < Nv) {
                float2 v0 = make_float2(acc[mt][nt][0], acc[mt][nt][1]);
                float2 v1 = make_float2(acc[mt][nt][2], acc[mt][nt][3]);
                if (ADDRES) {
                    float2 r0 = *(const float2*)(Res + (size_t)row0 * Nv + col);
                    float2 r1 = *(const float2*)(Res + (size_t)(row0 + 8) * Nv + col);
                    v0.x += r0.x; v0.y += r0.y; v1.x += r1.x; v1.y += r1.y;
                }
                *(float2*)(C + (size_t)row0 * Nv + col)       = v0;
                *(float2*)(C + (size_t)(row0 + 8) * Nv + col) = v1;
            }
        }
    }
}

__global__ void __launch_bounds__(256) gemm1_kernel(const float* __restrict__ A,
                                                    const float* __restrict__ W)
{
    gemm_tf32_body<3088, 512, true, false>(A, W, g_zx, nullptr);
}

__global__ void __launch_bounds__(256) gemm2_kernel(const float* __restrict__ W,
                                                    const float* __restrict__ Res)
{
    gemm_tf32_body<512, 1024, false, true>(g_g, W, g_res, Res);
}

// ---------------- conv1d (K=4, causal) + bias + silu + split ----------------------
__global__ void conv_kernel(const float* __restrict__ conv_w,
                            const float* __restrict__ conv_b)
{
    const int idx = blockIdx.x * blockDim.x + threadIdx.x; // [0, 8192*2048)
    const int c   = idx & 2047;
    const int row = idx >> 11;
    const int t   = row & (LL - 1);
    float acc = conv_b[c];
#pragma unroll
    for (int k = 0; k < 4; k++) {
        const int tt = t - 3 + k;
        if (tt >= 0)
            acc = fmaf(g_zx[(size_t)(row - (3 - k)) * 3088 + 1024 + c], conv_w[c * 4 + k], acc);
    }
    const float v = acc / (1.f + expf(-acc)); // silu
    if (c < 1024)       g_X [(size_t)row * 1024 + c]          = v;
    else if (c < 1536)  g_Bm[(size_t)row * 512  + (c - 1024)] = v;
    else                g_Cm[(size_t)row * 512  + (c - 1536)] = v;
}

// ---------------- dt / decay ------------------------------------------------------
__global__ void dt_kernel(const float* __restrict__ dt_bias,
                          const float* __restrict__ A_log)
{
    const int idx = blockIdx.x * blockDim.x + threadIdx.x; // [0, 8192*16)
    const int h   = idx & 15;
    const int row = idx >> 4;
    const float x  = g_zx[(size_t)row * 3088 + 3072 + h] + dt_bias[h];
    const float dt = (x > 20.f) ? x : log1pf(expf(x));
    g_dt [idx] = dt;
    g_dec[idx] = expf(-expf(A_log[h]) * dt);
}

// ---------------- selective scan --------------------------------------------------
__global__ void __launch_bounds__(128) scan_kernel()
{
    const int bx = blockIdx.x;
    const int nb = bx & 3;
    const int bh = bx >> 2;
    const int hh = bh & 15;
    const int bb = bh >> 4;
    const int tid  = threadIdx.x;
    const int n_l  = tid & 31;
    const int pq   = tid >> 5;
    const int pair = tid >> 1;
    const int half = tid & 1;
    const int rY   = pair >> 4;
    const int pY   = pair & 15;

    __shared__ __align__(16) float sB[4][32][4];
    __shared__ __align__(16) float sC[4][4][33];
    __shared__ __align__(16) float sX[4][64];
    __shared__ __align__(16) float sS[4][2];
    __shared__ __align__(16) float sH[2][16][33];

    const float* Bsrc = g_Bm  + (size_t)bb * LL * 512  + nb * 128;
    const float* Csrc = g_Cm  + (size_t)bb * LL * 512  + nb * 128;
    const float* Xsrc = g_X   + (size_t)bb * LL * 1024 + hh * 64;
    const float* Dsrc = g_dec + (size_t)bb * LL * 16   + hh;
    const float* Tsrc = g_dt  + (size_t)bb * LL * 16   + hh;
    float* Ydst = g_yp + (size_t)bx * LL * 64;

    for (int s = 0; s < 3; s++) {
        if (tid < 32) {
            float4 v = *(const float4*)(Bsrc + (size_t)s * 512 + tid * 4);
            *(float4*)&sB[s][tid][0] = v;
        } else if (tid < 64) {
            const int n = tid - 32;
            float4 v = *(const float4*)(Csrc + (size_t)s * 512 + n * 4);
            sC[s][0][n] = v.x; sC[s][1][n] = v.y; sC[s][2][n] = v.z; sC[s][3][n] = v.w;
        } else if (tid < 80) {
            const int i = tid - 64;
            float4 v = *(const float4*)(Xsrc + (size_t)s * 1024 + i * 4);
            *(float4*)&sX[s][i * 4] = v;
        } else if (tid == 80) sS[s][0] = Dsrc[(size_t)s * 16];
        else if (tid == 81)   sS[s][1] = Tsrc[(size_t)s * 16];
    }
    __syncthreads();

    float h0 = 0.f, h1 = 0.f, h2 = 0.f, h3 = 0.f;

    for (int t = 0; t < LL; t++) {
        const int cb = t & 3;
        const int hb = t & 1;
        const float4 Bv = *(const float4*)&sB[cb][n_l][0];
        const float dec = sS[cb][0];
        const float dtv = sS[cb][1];
        const float4 X0 = *(const float4*)&sX[cb][ 0 + pq * 4];
        const float4 X1 = *(const float4*)&sX[cb][16 + pq * 4];
        const float4 X2 = *(const float4*)&sX[cb][32 + pq * 4];
        const float4 X3 = *(const float4*)&sX[cb][48 + pq * 4];
        const float u0 = Bv.x * X0.x + Bv.y * X1.x + Bv.z * X2.x + Bv.w * X3.x;
        const float u1 = Bv.x * X0.y + Bv.y * X1.y + Bv.z * X2.y + Bv.w * X3.y;
        const float u2 = Bv.x * X0.z + Bv.y * X1.z + Bv.z * X2.z + Bv.w * X3.z;
        const float u3 = Bv.x * X0.w + Bv.y * X1.w + Bv.z * X2.w + Bv.w * X3.w;
        h0 = fmaf(dec, h0, dtv * u0);
        h1 = fmaf(dec, h1, dtv * u1);
        h2 = fmaf(dec, h2, dtv * u2);
        h3 = fmaf(dec, h3, dtv * u3);

        const int tp = t + 3;
        float4 rv = make_float4(0.f, 0.f, 0.f, 0.f);
        float  rsv = 0.f;
        const bool doPre = (tp < LL);
        if (doPre) {
            if (tid < 32)       rv = *(const float4*)(Bsrc + (size_t)tp * 512 + tid * 4);
            else if (tid < 64)  rv = *(const float4*)(Csrc + (size_t)tp * 512 + (tid - 32) * 4);
            else if (tid < 80)  rv = *(const float4*)(Xsrc + (size_t)tp * 1024 + (tid - 64) * 4);
            else if (tid == 80) rsv = Dsrc[(size_t)tp * 16];
            else if (tid == 81) rsv = Tsrc[(size_t)tp * 16];
        }

        const int pbase = pq * 4;
        sH[hb][pbase + 0][n_l] = h0;
        sH[hb][pbase + 1][n_l] = h1;
        sH[hb][pbase + 2][n_l] = h2;
        sH[hb][pbase + 3][n_l] = h3;
        __syncthreads();

        if (doPre) {
            const int buf = tp & 3;
            if (tid < 32) *(float4*)&sB[buf][tid][0] = rv;
            else if (tid < 64) {
                const int n = tid - 32;
                sC[buf][0][n] = rv.x; sC[buf][1][n] = rv.y; sC[buf][2][n] = rv.z; sC[buf][3][n] = rv.w;
            } else if (tid < 80) *(float4*)&sX[buf][(tid - 64) * 4] = rv;
            else if (tid == 80) sS[buf][0] = rsv;
            else if (tid == 81) sS[buf][1] = rsv;
        }

        const float* Crow = &sC[cb][rY][half * 16];
        const float* Hrow = &sH[hb][pY][half * 16];
        float acc = 0.f;
#pragma unroll
        for (int i = 0; i < 16; i++) acc = fmaf(Crow[i], Hrow[i], acc);
        acc += __shfl_xor_sync(0xffffffffu, acc, 1);
        if (half == 0) Ydst[(size_t)t * 64 + pair] = acc;
        __syncthreads();
    }
}

// ---------------- combine partials + D_skip + z-gate ------------------------------
__global__ void combine_kernel(const float* __restrict__ D_skip)
{
    const int idx = blockIdx.x * blockDim.x + threadIdx.x; // [0, 8192*1024)
    const int c    = idx & 1023;
    const int row  = idx >> 10;
    const int head = c >> 6;
    const int d    = c & 63;
    const int b    = row >> 11;
    const int t    = row & (LL - 1);
    const int base = (b * 16 + head) * 4;
    float y = 0.f;
#pragma unroll
    for (int nb = 0; nb < 4; nb++)
        y += g_yp[(size_t)(base + nb) * LL * 64 + (size_t)t * 64 + d];
    const float x = g_X[(size_t)row * 1024 + c];
    y += x * D_skip[head];
    const float z = g_zx[(size_t)row * 3088 + c];
    g_g[(size_t)row * 1024 + c] = y * (z / (1.f + expf(-z)));
}

// ---------------- RMSNorm ---------------------------------------------------------
__global__ void __launch_bounds__(256) rms_kernel(float* __restrict__ out)
{
    const int warp = threadIdx.x >> 5;
    const int lane = threadIdx.x & 31;
    const int row  = blockIdx.x * 8 + warp;
    const float* r = g_res + (size_t)row * 512;
    float v[16];
    float ss = 0.f;
#pragma unroll
    for (int i = 0; i < 16; i++) { v[i] = r[lane + i * 32]; ss = fmaf(v[i], v[i], ss); }
#pragma unroll
    for (int o = 16; o >= 1; o >>= 1) ss += __shfl_xor_sync(0xffffffffu, ss, o);
    const float sc = rsqrtf(ss * (1.f / 512.f) + 1e-5f);
    float* o = out + (size_t)row * 512;
#pragma unroll
    for (int i = 0; i < 16; i++) o[lane + i * 32] = v[i] * sc;
}

// ---------------- launch ----------------------------------------------------------
extern "C" void kernel_launch(void* const* d_in, const int* in_sizes, int n_in,
                              void* d_out, int out_size)
{
    const float* hs      = (const float*)d_in[0];
    const float* W_in    = (const float*)d_in[1];
    const float* conv_w  = (const float*)d_in[2];
    const float* conv_b  = (const float*)d_in[3];
    const float* dt_bias = (const float*)d_in[4];
    const float* A_log   = (const float*)d_in[5];
    const float* D_skip  = (const float*)d_in[6];
    const float* W_out   = (const float*)d_in[7];
    float* out = (float*)d_out;

    gemm1_kernel<<<dim3(25, 64), 256>>>(hs, W_in);
    conv_kernel<<<NROWS * 2048 / 256, 256>>>(conv_w, conv_b);
    dt_kernel<<<NROWS * 16 / 256, 256>>>(dt_bias, A_log);
    scan_kernel<<<256, 128>>>();
    combine_kernel<<<NROWS * 1024 / 256, 256>>>(D_skip);
    gemm2_kernel<<<dim3(4, 64), 256>>>(W_out, hs);
    rms_kernel<<<NROWS / 8, 256>>>(out);
}

// round 6
// speedup vs baseline: 1.5745x; 1.3632x over previous
#include <cuda_runtime.h>
#include <math.h>
#include <stdint.h>

#define LL 2048
#define NROWS 8192   // B*L

// ---------------- scratch (device globals; no runtime allocation) ----------------
static __device__ float g_zx [NROWS * 3088]; // zxbcdt
static __device__ float g_X  [NROWS * 1024]; // silu(conv) x part
static __device__ float g_Bm [NROWS * 512];
static __device__ float g_Cm [NROWS * 512];
static __device__ float g_dt [NROWS * 16];
static __device__ float g_dec[NROWS * 16];
static __device__ float g_yp [512 * LL * 64]; // y partials per (b,head,nblock16)
static __device__ float g_g  [NROWS * 1024]; // gated
static __device__ float g_res[NROWS * 512];  // pre-norm residual

// ---------------- tf32 helpers ----------------------------------------------------
__device__ __forceinline__ uint32_t f2tf32(float v) {
    uint32_t r;
    asm("cvt.rna.tf32.f32 %0, %1;" : "=r"(r) : "f"(v));
    return r;
}
__device__ __forceinline__ void split_tf32(float v, float& hi, float& lo) {
    uint32_t h = f2tf32(v);
    hi = __uint_as_float(h);
    float l = v - hi;                 // exact in fp32
    lo = __uint_as_float(f2tf32(l));
}
__device__ __forceinline__ void mma_tf32(float d[4],
                                         uint32_t a0, uint32_t a1, uint32_t a2, uint32_t a3,
                                         uint32_t b0, uint32_t b1) {
    asm volatile(
        "mma.sync.aligned.m16n8k8.row.col.f32.tf32.tf32.f32 "
        "{%0,%1,%2,%3}, {%4,%5,%6,%7}, {%8,%9}, {%0,%1,%2,%3};"
        : "+f"(d[0]), "+f"(d[1]), "+f"(d[2]), "+f"(d[3])
        : "r"(a0), "r"(a1), "r"(a2), "r"(a3), "r"(b0), "r"(b1));
}

// ---------------- cp.async helpers -------------------------------------------------
__device__ __forceinline__ void cp16(void* smem, const void* g) {
    uint32_t s = (uint32_t)__cvta_generic_to_shared(smem);
    asm volatile("cp.async.cg.shared.global [%0], [%1], 16;" :: "r"(s), "l"(g) : "memory");
}
__device__ __forceinline__ void cp4(void* smem, const void* g) {
    uint32_t s = (uint32_t)__cvta_generic_to_shared(smem);
    asm volatile("cp.async.ca.shared.global [%0], [%1], 4;" :: "r"(s), "l"(g) : "memory");
}
#define CP_COMMIT() asm volatile("cp.async.commit_group;" ::: "memory")
#define CP_WAIT5()  asm volatile("cp.async.wait_group 5;" ::: "memory")

// ---------------- TF32 tensor-core GEMM: C = A(MxK) @ B(KxN) [+ Res] --------------
template<int Nv, int Kv, bool GUARD, bool ADDRES>
__device__ __forceinline__ void gemm_tf32_body(const float* __restrict__ A,
                                               const float* __restrict__ Bw,
                                               float* __restrict__ C,
                                               const float* __restrict__ Res)
{
    __shared__ __align__(16) float sA[2][2][8][136]; // [buf][hi/lo][k][row]
    __shared__ __align__(16) float sB[2][2][8][136]; // [buf][hi/lo][k][col]

    const int tid   = threadIdx.x;
    const int warp  = tid >> 5;
    const int lane  = tid & 31;
    const int gid   = lane >> 2;   // 0..7
    const int tig   = lane & 3;    // 0..3
    const int warpM = warp & 1;    // 0..1 (64 rows each)
    const int warpN = warp >> 1;   // 0..3 (32 cols each)

    const int aRow = tid >> 1;         // 0..127
    const int aCol = (tid & 1) * 4;    // 0 or 4
    const int bRow = tid >> 5;         // 0..7
    const int bCol = (tid & 31) * 4;   // 0..124

    const int nbase = blockIdx.x * 128;
    const int mbase = blockIdx.y * 128;
    const float* Ap = A + (size_t)(mbase + aRow) * Kv + aCol;
    const float* Bp = Bw + (size_t)bRow * Nv + nbase + bCol;
    const bool  bOK = (!GUARD) || (nbase + bCol + 3 < Nv);

    float acc[4][4][4];
#pragma unroll
    for (int mt = 0; mt < 4; mt++)
#pragma unroll
        for (int nt = 0; nt < 4; nt++)
#pragma unroll
            for (int i = 0; i < 4; i++) acc[mt][nt][i] = 0.f;

    {
        float4 av = *(const float4*)Ap;
        float4 bv = bOK ? *(const float4*)Bp : make_float4(0.f,0.f,0.f,0.f);
        float h, l;
        split_tf32(av.x, h, l); sA[0][0][aCol+0][aRow] = h; sA[0][1][aCol+0][aRow] = l;
        split_tf32(av.y, h, l); sA[0][0][aCol+1][aRow] = h; sA[0][1][aCol+1][aRow] = l;
        split_tf32(av.z, h, l); sA[0][0][aCol+2][aRow] = h; sA[0][1][aCol+2][aRow] = l;
        split_tf32(av.w, h, l); sA[0][0][aCol+3][aRow] = h; sA[0][1][aCol+3][aRow] = l;
        float4 bh, bl;
        split_tf32(bv.x, bh.x, bl.x); split_tf32(bv.y, bh.y, bl.y);
        split_tf32(bv.z, bh.z, bl.z); split_tf32(bv.w, bh.w, bl.w);
        *(float4*)&sB[0][0][bRow][bCol] = bh;
        *(float4*)&sB[0][1][bRow][bCol] = bl;
    }
    __syncthreads();

    const int NK = Kv / 8;
    for (int ks = 0; ks < NK; ks++) {
        const int buf = ks & 1;
        float4 av, bv;
        const bool hasNext = (ks + 1 < NK);
        if (hasNext) {
            av = *(const float4*)(Ap + (ks + 1) * 8);
            bv = bOK ? *(const float4*)(Bp + (size_t)(ks + 1) * 8 * Nv)
                     : make_float4(0.f,0.f,0.f,0.f);
        }

        const float (*Ah)[136] = sA[buf][0];
        const float (*Al)[136] = sA[buf][1];
        const float (*Bh)[136] = sB[buf][0];
        const float (*Bl)[136] = sB[buf][1];

        uint32_t ah[4][4], al[4][4], bh[4][2], bl[4][2];
#pragma unroll
        for (int mt = 0; mt < 4; mt++) {
            const int r = warpM * 64 + mt * 16 + gid;
            ah[mt][0] = __float_as_uint(Ah[tig    ][r    ]);
            ah[mt][1] = __float_as_uint(Ah[tig    ][r + 8]);
            ah[mt][2] = __float_as_uint(Ah[tig + 4][r    ]);
            ah[mt][3] = __float_as_uint(Ah[tig + 4][r + 8]);
            al[mt][0] = __float_as_uint(Al[tig    ][r    ]);
            al[mt][1] = __float_as_uint(Al[tig    ][r + 8]);
            al[mt][2] = __float_as_uint(Al[tig + 4][r    ]);
            al[mt][3] = __float_as_uint(Al[tig + 4][r + 8]);
        }
#pragma unroll
        for (int nt = 0; nt < 4; nt++) {
            const int c = warpN * 32 + nt * 8 + gid;
            bh[nt][0] = __float_as_uint(Bh[tig    ][c]);
            bh[nt][1] = __float_as_uint(Bh[tig + 4][c]);
            bl[nt][0] = __float_as_uint(Bl[tig    ][c]);
            bl[nt][1] = __float_as_uint(Bl[tig + 4][c]);
        }

#pragma unroll
        for (int mt = 0; mt < 4; mt++)
#pragma unroll
            for (int nt = 0; nt < 4; nt++) {
                mma_tf32(acc[mt][nt], ah[mt][0], ah[mt][1], ah[mt][2], ah[mt][3],
                         bh[nt][0], bh[nt][1]);
                mma_tf32(acc[mt][nt], ah[mt][0], ah[mt][1], ah[mt][2], ah[mt][3],
                         bl[nt][0], bl[nt][1]);
                mma_tf32(acc[mt][nt], al[mt][0], al[mt][1], al[mt][2], al[mt][3],
                         bh[nt][0], bh[nt][1]);
            }

        if (hasNext) {
            const int nb = buf ^ 1;
            float h, l;
            split_tf32(av.x, h, l); sA[nb][0][aCol+0][aRow] = h; sA[nb][1][aCol+0][aRow] = l;
            split_tf32(av.y, h, l); sA[nb][0][aCol+1][aRow] = h; sA[nb][1][aCol+1][aRow] = l;
            split_tf32(av.z, h, l); sA[nb][0][aCol+2][aRow] = h; sA[nb][1][aCol+2][aRow] = l;
            split_tf32(av.w, h, l); sA[nb][0][aCol+3][aRow] = h; sA[nb][1][aCol+3][aRow] = l;
            float4 bhh, bll;
            split_tf32(bv.x, bhh.x, bll.x); split_tf32(bv.y, bhh.y, bll.y);
            split_tf32(bv.z, bhh.z, bll.z); split_tf32(bv.w, bhh.w, bll.w);
            *(float4*)&sB[nb][0][bRow][bCol] = bhh;
            *(float4*)&sB[nb][1][bRow][bCol] = bll;
        }
        __syncthreads();
    }

#pragma unroll
    for (int mt = 0; mt < 4; mt++) {
        const int row0 = mbase + warpM * 64 + mt * 16 + gid;
#pragma unroll
        for (int nt = 0; nt < 4; nt++) {
            const int col = nbase + warpN * 32 + nt * 8 + tig * 2;
            if (!GUARD || col < Nv) {
                float2 v0 = make_float2(acc[mt][nt][0], acc[mt][nt][1]);
                float2 v1 = make_float2(acc[mt][nt][2], acc[mt][nt][3]);
                if (ADDRES) {
                    float2 r0 = *(const float2*)(Res + (size_t)row0 * Nv + col);
                    float2 r1 = *(const float2*)(Res + (size_t)(row0 + 8) * Nv + col);
                    v0.x += r0.x; v0.y += r0.y; v1.x += r1.x; v1.y += r1.y;
                }
                *(float2*)(C + (size_t)row0 * Nv + col)       = v0;
                *(float2*)(C + (size_t)(row0 + 8) * Nv + col) = v1;
            }
        }
    }
}

__global__ void __launch_bounds__(256) gemm1_kernel(const float* __restrict__ A,
                                                    const float* __restrict__ W)
{
    gemm_tf32_body<3088, 512, true, false>(A, W, g_zx, nullptr);
}

__global__ void __launch_bounds__(256) gemm2_kernel(const float* __restrict__ W,
                                                    const float* __restrict__ Res)
{
    gemm_tf32_body<512, 1024, false, true>(g_g, W, g_res, Res);
}

// ---------------- conv1d (K=4, causal) + bias + silu + split ----------------------
__global__ void conv_kernel(const float* __restrict__ conv_w,
                            const float* __restrict__ conv_b)
{
    const int idx = blockIdx.x * blockDim.x + threadIdx.x; // [0, 8192*2048)
    const int c   = idx & 2047;
    const int row = idx >> 11;
    const int t   = row & (LL - 1);
    float acc = conv_b[c];
#pragma unroll
    for (int k = 0; k < 4; k++) {
        const int tt = t - 3 + k;
        if (tt >= 0)
            acc = fmaf(g_zx[(size_t)(row - (3 - k)) * 3088 + 1024 + c], conv_w[c * 4 + k], acc);
    }
    const float v = acc / (1.f + expf(-acc)); // silu
    if (c < 1024)       g_X [(size_t)row * 1024 + c]          = v;
    else if (c < 1536)  g_Bm[(size_t)row * 512  + (c - 1024)] = v;
    else                g_Cm[(size_t)row * 512  + (c - 1536)] = v;
}

// ---------------- dt / decay ------------------------------------------------------
__global__ void dt_kernel(const float* __restrict__ dt_bias,
                          const float* __restrict__ A_log)
{
    const int idx = blockIdx.x * blockDim.x + threadIdx.x; // [0, 8192*16)
    const int h   = idx & 15;
    const int row = idx >> 4;
    const float x  = g_zx[(size_t)row * 3088 + 3072 + h] + dt_bias[h];
    const float dt = (x > 20.f) ? x : log1pf(expf(x));
    g_dt [idx] = dt;
    g_dec[idx] = expf(-expf(A_log[h]) * dt);
}

// ---------------- selective scan v2 ------------------------------------------------
// Grid: 512 CTAs = (b, head, nblock of 16 states). 128 threads.
// cp.async 8-deep pipeline (prefetch distance 6, wait_group 5), ONE barrier/iter.
// Update threads: (n_l = tid&15, pq = tid>>4) own h[n_l][2 p's].
// y threads: pair = tid>>1 -> (rY = pair>>4, pY = pair&15), 8-term partial + shfl.
__global__ void __launch_bounds__(128) scan_kernel()
{
    const int bx = blockIdx.x;
    const int nb = bx & 7;          // 16-state block
    const int bh = bx >> 3;
    const int hh = bh & 15;
    const int bb = bh >> 4;
    const int tid  = threadIdx.x;
    const int n_l  = tid & 15;
    const int pq   = tid >> 4;      // 0..7
    const int pair = tid >> 1;      // 0..63
    const int half = tid & 1;
    const int rY   = pair >> 4;     // 0..3
    const int pY   = pair & 15;     // 0..15

    __shared__ __align__(16) float sB[8][16][4];
    __shared__ __align__(16) float sC[8][16][4];
    __shared__ __align__(16) float sX[8][64];
    __shared__ __align__(16) float sS[8][2];
    __shared__ __align__(16) float sH[2][16][17];

    const float* Bsrc = g_Bm  + (size_t)bb * LL * 512  + nb * 64;
    const float* Csrc = g_Cm  + (size_t)bb * LL * 512  + nb * 64;
    const float* Xsrc = g_X   + (size_t)bb * LL * 1024 + hh * 64;
    const float* Dsrc = g_dec + (size_t)bb * LL * 16   + hh;
    const float* Tsrc = g_dt  + (size_t)bb * LL * 16   + hh;
    float* Ydst = g_yp + (size_t)bx * LL * 64;

    // loader routing: tid 0-15 B, 16-31 C, 32-47 X, 48 dec, 49 dt
    const int li = tid & 15;

    // prologue: issue steps 0..5 as 6 groups
#pragma unroll
    for (int s = 0; s < 6; s++) {
        if (tid < 16)       cp16(&sB[s][li][0], Bsrc + (size_t)s * 512  + li * 4);
        else if (tid < 32)  cp16(&sC[s][li][0], Csrc + (size_t)s * 512  + li * 4);
        else if (tid < 48)  cp16(&sX[s][li * 4], Xsrc + (size_t)s * 1024 + li * 4);
        else if (tid == 48) cp4(&sS[s][0], Dsrc + (size_t)s * 16);
        else if (tid == 49) cp4(&sS[s][1], Tsrc + (size_t)s * 16);
        CP_COMMIT();
    }
    CP_WAIT5();
    __syncthreads();

    float h0 = 0.f, h1 = 0.f;
    const int p0 = pq * 2;
    const int p1 = p0 + 1;

    for (int t = 0; t < LL; t++) {
        const int cb = t & 7;
        const int hb = t & 1;

        // ---- state update ----
        const float4 Bv  = *(const float4*)&sB[cb][n_l][0];
        const float  dec = sS[cb][0];
        const float  dtv = sS[cb][1];
        const float u0 = (Bv.x * sX[cb][ 0 + p0] + Bv.y * sX[cb][16 + p0])
                       + (Bv.z * sX[cb][32 + p0] + Bv.w * sX[cb][48 + p0]);
        const float u1 = (Bv.x * sX[cb][ 0 + p1] + Bv.y * sX[cb][16 + p1])
                       + (Bv.z * sX[cb][32 + p1] + Bv.w * sX[cb][48 + p1]);
        h0 = fmaf(dec, h0, dtv * u0);
        h1 = fmaf(dec, h1, dtv * u1);
        sH[hb][p0][n_l] = h0;
        sH[hb][p1][n_l] = h1;

        // ---- prefetch step t+6 (buffer (t+6)&7) ----
        const int ts = t + 6;
        if (ts < LL) {
            const int sb = ts & 7;
            if (tid < 16)       cp16(&sB[sb][li][0], Bsrc + (size_t)ts * 512  + li * 4);
            else if (tid < 32)  cp16(&sC[sb][li][0], Csrc + (size_t)ts * 512  + li * 4);
            else if (tid < 48)  cp16(&sX[sb][li * 4], Xsrc + (size_t)ts * 1024 + li * 4);
            else if (tid == 48) cp4(&sS[sb][0], Dsrc + (size_t)ts * 16);
            else if (tid == 49) cp4(&sS[sb][1], Tsrc + (size_t)ts * 16);
        }
        CP_COMMIT();
        CP_WAIT5();
        __syncthreads();

        // ---- y partial: y(rY,pY) over this CTA's 16 states ----
        const float* Cc = &sC[cb][half * 8][0];
        const float* Hh = &sH[hb][pY][half * 8];
        float a0 = 0.f, a1 = 0.f;
#pragma unroll
        for (int i = 0; i < 4; i++) {
            a0 = fmaf(Cc[(2 * i    ) * 4 + rY], Hh[2 * i    ], a0);
            a1 = fmaf(Cc[(2 * i + 1) * 4 + rY], Hh[2 * i + 1], a1);
        }
        float acc = a0 + a1;
        acc += __shfl_xor_sync(0xffffffffu, acc, 1);
        if (half == 0) Ydst[(size_t)t * 64 + pair] = acc;
    }
}

// ---------------- combine partials + D_skip + z-gate ------------------------------
__global__ void combine_kernel(const float* __restrict__ D_skip)
{
    const int idx = blockIdx.x * blockDim.x + threadIdx.x; // [0, 8192*1024)
    const int c    = idx & 1023;
    const int row  = idx >> 10;
    const int head = c >> 6;
    const int d    = c & 63;
    const int b    = row >> 11;
    const int t    = row & (LL - 1);
    const int base = (b * 16 + head) * 8;
    float y = 0.f;
#pragma unroll
    for (int nb = 0; nb < 8; nb++)
        y += g_yp[(size_t)(base + nb) * LL * 64 + (size_t)t * 64 + d];
    const float x = g_X[(size_t)row * 1024 + c];
    y += x * D_skip[head];
    const float z = g_zx[(size_t)row * 3088 + c];
    g_g[(size_t)row * 1024 + c] = y * (z / (1.f + expf(-z)));
}

// ---------------- RMSNorm ---------------------------------------------------------
__global__ void __launch_bounds__(256) rms_kernel(float* __restrict__ out)
{
    const int warp = threadIdx.x >> 5;
    const int lane = threadIdx.x & 31;
    const int row  = blockIdx.x * 8 + warp;
    const float* r = g_res + (size_t)row * 512;
    float v[16];
    float ss = 0.f;
#pragma unroll
    for (int i = 0; i < 16; i++) { v[i] = r[lane + i * 32]; ss = fmaf(v[i], v[i], ss); }
#pragma unroll
    for (int o = 16; o >= 1; o >>= 1) ss += __shfl_xor_sync(0xffffffffu, ss, o);
    const float sc = rsqrtf(ss * (1.f / 512.f) + 1e-5f);
    float* o = out + (size_t)row * 512;
#pragma unroll
    for (int i = 0; i < 16; i++) o[lane + i * 32] = v[i] * sc;
}

// ---------------- launch ----------------------------------------------------------
extern "C" void kernel_launch(void* const* d_in, const int* in_sizes, int n_in,
                              void* d_out, int out_size)
{
    const float* hs      = (const float*)d_in[0];
    const float* W_in    = (const float*)d_in[1];
    const float* conv_w  = (const float*)d_in[2];
    const float* conv_b  = (const float*)d_in[3];
    const float* dt_bias = (const float*)d_in[4];
    const float* A_log   = (const float*)d_in[5];
    const float* D_skip  = (const float*)d_in[6];
    const float* W_out   = (const float*)d_in[7];
    float* out = (float*)d_out;

    gemm1_kernel<<<dim3(25, 64), 256>>>(hs, W_in);
    conv_kernel<<<NROWS * 2048 / 256, 256>>>(conv_w, conv_b);
    dt_kernel<<<NROWS * 16 / 256, 256>>>(dt_bias, A_log);
    scan_kernel<<<512, 128>>>();
    combine_kernel<<<NROWS * 1024 / 256, 256>>>(D_skip);
    gemm2_kernel<<<dim3(4, 64), 256>>>(W_out, hs);
    rms_kernel<<<NROWS / 8, 256>>>(out);
}